// round 9
// baseline (speedup 1.0000x reference)
#include <cuda_runtime.h>
#include <cuda_bf16.h>
#include <cstddef>

// Fused YOLOv3 decode. Block-specialized single kernel (structure from R8,
// which compiled lean at 48 regs but SPILLED under the (256,5)=51-reg cap ->
// 182MB traffic vs 120MB workload). This round: (256,4)=64-reg cap — enough
// for the float2 batch, still 4 blocks/SM (50% occ).
//   blocks [0, pairBlocks)   : float2 path, scales 26 & 52, 2 cells/thread
//   blocks [pairBlocks, end) : scalar path, scale 13
// Argmax stays exact (norm-based rel_err is dominated by the cls field; even
// a few class flips would exceed 1e-3).

__device__ __forceinline__ float sigf(float x) { return 1.0f / (1.0f + __expf(-x)); }

__global__ __launch_bounds__(256, 4)
void yolo_decode_r9(const float* __restrict__ o13,
                    const float* __restrict__ o26,
                    const float* __restrict__ o52,
                    const float* __restrict__ a13,
                    const float* __restrict__ a26,
                    const float* __restrict__ a52,
                    const float* __restrict__ threshp,
                    const int*   __restrict__ casep,
                    float* __restrict__ boxes,   // [N,6]
                    float* __restrict__ mask,    // [N]
                    int B, int pairBlocks)
{
    const int C13 = B * 13 * 13;
    const int C26 = B * 26 * 26;
    const int C52 = B * 52 * 52;
    const int P26 = C26 >> 1;
    const int P52 = C52 >> 1;

    const int iv = __ldg(casep);
    const float case_f = (iv > 0 && iv < 1000000) ? (float)iv : __int_as_float(iv);
    const float inv_case = 1.0f / case_f;
    const float thresh = __ldg(threshp);

    if (blockIdx.x < pairBlocks) {
        // ---------------- float2 pair path: scales 26 & 52 ----------------
        const int p = blockIdx.x * blockDim.x + threadIdx.x;
        const int npair = 3 * (P26 + P52);
        if (p >= npair) return;

        const float* in; const float* anch;
        int S, HW, Pc, q, rowoff; float t;
        if (p < 3 * P26) { in = o26; anch = a26; S = 26; HW = 676;  Pc = P26;
                           q = p;            rowoff = C13 * 3;         t = 16.0f; }
        else             { in = o52; anch = a52; S = 52; HW = 2704; Pc = P52;
                           q = p - 3 * P26;  rowoff = (C13 + C26) * 3; t = 8.0f;  }
        const float scale = t * inv_case;

        const int a     = q / Pc;
        const int pairi = q - a * Pc;
        const int local = pairi << 1;
        const int b     = local / HW;
        const int pos   = local - b * HW;      // even, pos+1 < HW

        const float* ptr = in + (size_t)(b * 255 + a * 85) * HW + pos;  // 8B aligned

        const float2 q0 = *(const float2*)(ptr);
        const float2 q1 = *(const float2*)(ptr + HW);
        const float2 q2 = *(const float2*)(ptr + 2 * HW);
        const float2 q3 = *(const float2*)(ptr + 3 * HW);
        const float2 q4 = *(const float2*)(ptr + 4 * HW);

        // argmax over 80 class channels for both cells, float2 batches of 8.
        // Strict '>' keeps FIRST max (jnp.argmax tie rule). EXACT compares.
        float mx0 = -3.4e38f, mx1 = -3.4e38f;
        int   c0 = 0, c1 = 0;
        const float* pc = ptr + 5 * HW;
        #pragma unroll
        for (int d0 = 0; d0 < 80; d0 += 8) {
            float2 v[8];
            #pragma unroll
            for (int i = 0; i < 8; ++i)
                v[i] = *(const float2*)(pc + (d0 + i) * HW);
            #pragma unroll
            for (int i = 0; i < 8; ++i) {
                const int d = d0 + i;
                if (v[i].x > mx0) { mx0 = v[i].x; c0 = d; }
                if (v[i].y > mx1) { mx1 = v[i].y; c1 = d; }
            }
        }

        const float ax = __ldg(anch + a * 2 + 0);
        const float ay = __ldg(anch + a * 2 + 1);

        const int h0 = pos / S;
        const int w0 = pos - h0 * S;           // even -> w0+1 <= S-1, no wrap

        // cell 0
        {
            const int row = rowoff + local * 3 + a;
            float* r = boxes + (size_t)row * 6;
            *(float2*)(r)     = make_float2(sigf(q0.x), ((float)w0 + q1.x) * scale);
            *(float2*)(r + 2) = make_float2(((float)h0 + q2.x) * scale,
                                            ax * __expf(q3.x) * inv_case);
            *(float2*)(r + 4) = make_float2(ay * __expf(q4.x) * inv_case, (float)c0);
            mask[row] = (q0.x > thresh) ? 1.0f : 0.0f;
        }
        // cell 1
        {
            const int row = rowoff + (local + 1) * 3 + a;
            float* r = boxes + (size_t)row * 6;
            *(float2*)(r)     = make_float2(sigf(q0.y), ((float)(w0 + 1) + q1.y) * scale);
            *(float2*)(r + 2) = make_float2(((float)h0 + q2.y) * scale,
                                            ax * __expf(q3.y) * inv_case);
            *(float2*)(r + 4) = make_float2(ay * __expf(q4.y) * inv_case, (float)c1);
            mask[row] = (q0.y > thresh) ? 1.0f : 0.0f;
        }
    } else {
        // ---------------- scalar path: scale 13 ----------------
        const int idx = (blockIdx.x - pairBlocks) * blockDim.x + threadIdx.x;
        if (idx >= 3 * C13) return;

        const int a     = idx / C13;
        const int local = idx - a * C13;
        const int HW = 169, S = 13;
        const int b   = local / HW;
        const int pos = local - b * HW;
        const int h   = pos / S;
        const int w   = pos - h * S;
        const float scale = 32.0f * inv_case;

        const float* ptr = o13 + (size_t)(b * 255 + a * 85) * HW + pos;

        const float v0 = __ldg(ptr);
        const float v1 = __ldg(ptr + HW);
        const float v2 = __ldg(ptr + 2 * HW);
        const float v3 = __ldg(ptr + 3 * HW);
        const float v4 = __ldg(ptr + 4 * HW);

        float maxv = -3.4e38f; int cls = 0;
        const float* pc = ptr + 5 * HW;
        #pragma unroll
        for (int d0 = 0; d0 < 80; d0 += 10) {
            float v[10];
            #pragma unroll
            for (int i = 0; i < 10; ++i) v[i] = __ldg(pc + (d0 + i) * HW);
            #pragma unroll
            for (int i = 0; i < 10; ++i)
                if (v[i] > maxv) { maxv = v[i]; cls = d0 + i; }
        }

        const int row = local * 3 + a;
        float* r = boxes + (size_t)row * 6;
        *(float2*)(r)     = make_float2(sigf(v0), ((float)w + v1) * scale);
        *(float2*)(r + 2) = make_float2(((float)h + v2) * scale,
                                        __ldg(a13 + a * 2 + 0) * __expf(v3) * inv_case);
        *(float2*)(r + 4) = make_float2(__ldg(a13 + a * 2 + 1) * __expf(v4) * inv_case,
                                        (float)cls);
        mask[row] = (v0 > thresh) ? 1.0f : 0.0f;
    }
}

extern "C" void kernel_launch(void* const* d_in, const int* in_sizes, int n_in,
                              void* d_out, int out_size)
{
    const float* o13 = (const float*)d_in[0];
    const float* o26 = (const float*)d_in[1];
    const float* o52 = (const float*)d_in[2];
    const float* a13 = (const float*)d_in[3];
    const float* a26 = (const float*)d_in[4];
    const float* a52 = (const float*)d_in[5];
    const float* th  = (const float*)d_in[6];
    const int*   cs  = (const int*)  d_in[7];

    const int B = in_sizes[0] / (255 * 13 * 13);

    const int C13 = B * 13 * 13;
    const int C26 = B * 26 * 26;
    const int C52 = B * 52 * 52;
    const int N = (C13 + C26 + C52) * 3;

    float* boxes = (float*)d_out;                   // [N,6]
    float* mask  = (float*)d_out + (size_t)N * 6;   // [N]

    const int TPB = 256;
    const int npair = 3 * ((C26 >> 1) + (C52 >> 1));
    const int pairBlocks = (npair + TPB - 1) / TPB;
    const int s13Blocks  = (3 * C13 + TPB - 1) / TPB;

    yolo_decode_r9<<<pairBlocks + s13Blocks, TPB>>>(
        o13, o26, o52, a13, a26, a52, th, cs, boxes, mask, B, pairBlocks);
}

// round 10
// speedup vs baseline: 1.7267x; 1.7267x over previous
#include <cuda_runtime.h>
#include <cuda_bf16.h>
#include <cstddef>

// Fused YOLOv3 decode. Diagnosis chain:
//  - scalar best (29.4us) is LSU-issue bound: 29M LDG.b32 ~ 3.3/cyc/SM > 2.2 cap
//  - all wide-load attempts spilled because full unroll lets ptxas front-batch
//    loads past the register budget (traffic 157-182MB vs 120MB workload)
// Fix: float4 quad path (7.2M LDGs) + block-specialized paths + the argmax
// outer loop at "#pragma unroll 1" so live state = ONE v[4] batch, under a
// (256,4)=64-reg cap.
//   blocks [0, quadBlocks)  : float4 path, scales 26 & 52, 4 cells/thread
//   blocks [quadBlocks, ..) : scalar path, scale 13 (HW=169 not /4)

__device__ __forceinline__ float sigf(float x) { return 1.0f / (1.0f + __expf(-x)); }

__global__ __launch_bounds__(256, 4)
void yolo_decode_r10(const float* __restrict__ o13,
                     const float* __restrict__ o26,
                     const float* __restrict__ o52,
                     const float* __restrict__ a13,
                     const float* __restrict__ a26,
                     const float* __restrict__ a52,
                     const float* __restrict__ threshp,
                     const int*   __restrict__ casep,
                     float* __restrict__ boxes,   // [N,6]
                     float* __restrict__ mask,    // [N]
                     int B, int quadBlocks)
{
    const int C13 = B * 13 * 13;
    const int C26 = B * 26 * 26;
    const int C52 = B * 52 * 52;
    const int Q26 = C26 >> 2;
    const int Q52 = C52 >> 2;

    const int iv = __ldg(casep);
    const float case_f = (iv > 0 && iv < 1000000) ? (float)iv : __int_as_float(iv);
    const float inv_case = 1.0f / case_f;
    const float thresh = __ldg(threshp);

    if (blockIdx.x < quadBlocks) {
        // ---------------- float4 quad path: scales 26 & 52 ----------------
        const int p = blockIdx.x * blockDim.x + threadIdx.x;
        const int nquad = 3 * (Q26 + Q52);
        if (p >= nquad) return;

        const float* in; const float* anch;
        int S, HW, Qc, q, rowoff; float t;
        if (p < 3 * Q26) { in = o26; anch = a26; S = 26; HW = 676;  Qc = Q26;
                           q = p;            rowoff = C13 * 3;         t = 16.0f; }
        else             { in = o52; anch = a52; S = 52; HW = 2704; Qc = Q52;
                           q = p - 3 * Q26;  rowoff = (C13 + C26) * 3; t = 8.0f;  }
        const float scale = t * inv_case;

        const int a     = q / Qc;
        const int quadi = q - a * Qc;
        const int local = quadi << 2;
        const int b     = local / HW;
        const int pos   = local - b * HW;      // pos%4==0, pos+3 < HW

        const float* ptr = in + (size_t)(b * 255 + a * 85) * HW + pos;  // 16B aligned

        const float4 q0 = *(const float4*)(ptr);
        const float4 q1 = *(const float4*)(ptr + HW);
        const float4 q2 = *(const float4*)(ptr + 2 * HW);
        const float4 q3 = *(const float4*)(ptr + 3 * HW);
        const float4 q4 = *(const float4*)(ptr + 4 * HW);

        // Argmax over 80 class channels for 4 cells. Outer loop NOT unrolled:
        // keeps exactly one v[4] batch live (ptxas cannot front-batch loads
        // across iterations and spill). Strict '>' keeps FIRST max.
        float mx0 = -3.4e38f, mx1 = -3.4e38f, mx2 = -3.4e38f, mx3 = -3.4e38f;
        int   c0 = 0, c1 = 0, c2 = 0, c3 = 0;
        const float* pc = ptr + 5 * HW;
        #pragma unroll 1
        for (int d0 = 0; d0 < 80; d0 += 4) {
            float4 v[4];
            #pragma unroll
            for (int i = 0; i < 4; ++i)
                v[i] = *(const float4*)(pc + (d0 + i) * HW);
            #pragma unroll
            for (int i = 0; i < 4; ++i) {
                const int d = d0 + i;
                if (v[i].x > mx0) { mx0 = v[i].x; c0 = d; }
                if (v[i].y > mx1) { mx1 = v[i].y; c1 = d; }
                if (v[i].z > mx2) { mx2 = v[i].z; c2 = d; }
                if (v[i].w > mx3) { mx3 = v[i].w; c3 = d; }
            }
        }

        const float ax = __ldg(anch + a * 2 + 0);
        const float ay = __ldg(anch + a * 2 + 1);

        const int h0 = pos / S;
        const int w0 = pos - h0 * S;

        const float oo[4] = {q0.x, q0.y, q0.z, q0.w};
        const float ox[4] = {q1.x, q1.y, q1.z, q1.w};
        const float oy[4] = {q2.x, q2.y, q2.z, q2.w};
        const float ow[4] = {q3.x, q3.y, q3.z, q3.w};
        const float oh[4] = {q4.x, q4.y, q4.z, q4.w};
        const int   cl[4] = {c0, c1, c2, c3};

        #pragma unroll
        for (int i = 0; i < 4; ++i) {
            int wi = w0 + i, hi = h0;
            if (wi >= S) { wi -= S; hi += 1; }   // at most one row wrap (4 <= S)

            const int row = rowoff + (local + i) * 3 + a;
            float* r = boxes + (size_t)row * 6;
            *(float2*)(r)     = make_float2(sigf(oo[i]), ((float)wi + ox[i]) * scale);
            *(float2*)(r + 2) = make_float2(((float)hi + oy[i]) * scale,
                                            ax * __expf(ow[i]) * inv_case);
            *(float2*)(r + 4) = make_float2(ay * __expf(oh[i]) * inv_case, (float)cl[i]);
            mask[row] = (oo[i] > thresh) ? 1.0f : 0.0f;
        }
    } else {
        // ---------------- scalar path: scale 13 ----------------
        const int idx = (blockIdx.x - quadBlocks) * blockDim.x + threadIdx.x;
        if (idx >= 3 * C13) return;

        const int a     = idx / C13;
        const int local = idx - a * C13;
        const int HW = 169, S = 13;
        const int b   = local / HW;
        const int pos = local - b * HW;
        const int h   = pos / S;
        const int w   = pos - h * S;
        const float scale = 32.0f * inv_case;

        const float* ptr = o13 + (size_t)(b * 255 + a * 85) * HW + pos;

        const float v0 = __ldg(ptr);
        const float v1 = __ldg(ptr + HW);
        const float v2 = __ldg(ptr + 2 * HW);
        const float v3 = __ldg(ptr + 3 * HW);
        const float v4 = __ldg(ptr + 4 * HW);

        float maxv = -3.4e38f; int cls = 0;
        const float* pc = ptr + 5 * HW;
        #pragma unroll 1
        for (int d0 = 0; d0 < 80; d0 += 8) {
            float v[8];
            #pragma unroll
            for (int i = 0; i < 8; ++i) v[i] = __ldg(pc + (d0 + i) * HW);
            #pragma unroll
            for (int i = 0; i < 8; ++i)
                if (v[i] > maxv) { maxv = v[i]; cls = d0 + i; }
        }

        const int row = local * 3 + a;
        float* r = boxes + (size_t)row * 6;
        *(float2*)(r)     = make_float2(sigf(v0), ((float)w + v1) * scale);
        *(float2*)(r + 2) = make_float2(((float)h + v2) * scale,
                                        __ldg(a13 + a * 2 + 0) * __expf(v3) * inv_case);
        *(float2*)(r + 4) = make_float2(__ldg(a13 + a * 2 + 1) * __expf(v4) * inv_case,
                                        (float)cls);
        mask[row] = (v0 > thresh) ? 1.0f : 0.0f;
    }
}

extern "C" void kernel_launch(void* const* d_in, const int* in_sizes, int n_in,
                              void* d_out, int out_size)
{
    const float* o13 = (const float*)d_in[0];
    const float* o26 = (const float*)d_in[1];
    const float* o52 = (const float*)d_in[2];
    const float* a13 = (const float*)d_in[3];
    const float* a26 = (const float*)d_in[4];
    const float* a52 = (const float*)d_in[5];
    const float* th  = (const float*)d_in[6];
    const int*   cs  = (const int*)  d_in[7];

    const int B = in_sizes[0] / (255 * 13 * 13);

    const int C13 = B * 13 * 13;
    const int C26 = B * 26 * 26;
    const int C52 = B * 52 * 52;
    const int N = (C13 + C26 + C52) * 3;

    float* boxes = (float*)d_out;                   // [N,6]
    float* mask  = (float*)d_out + (size_t)N * 6;   // [N]

    const int TPB = 256;
    const int nquad = 3 * ((C26 >> 2) + (C52 >> 2));
    const int quadBlocks = (nquad + TPB - 1) / TPB;
    const int s13Blocks  = (3 * C13 + TPB - 1) / TPB;

    yolo_decode_r10<<<quadBlocks + s13Blocks, TPB>>>(
        o13, o26, o52, a13, a26, a52, th, cs, boxes, mask, B, quadBlocks);
}

// round 11
// speedup vs baseline: 2.3656x; 1.3700x over previous
#include <cuda_runtime.h>
#include <cuda_bf16.h>
#include <cstddef>

// Fused YOLOv3 decode. R10 proved the no-spill quad skeleton (traffic=120MB
// exact) but starved: MLP=4/iter and 2.6 blocks/SM. R11:
//  - box channels loaded AND written BEFORE the argmax loop -> their 20 regs
//    die early, making room for a float4 v[10] batch (MLP=10, 5KB/warp/iter)
//    under the same 64-reg cap (#pragma unroll 1 still blocks front-batching)
//  - 128-thread blocks, launch_bounds(128,8): grid 761 -> 5.1 blocks/SM
//   blocks [0, quadBlocks)  : float4 path, scales 26 & 52, 4 cells/thread
//   blocks [quadBlocks, ..) : scalar path, scale 13 (HW=169 not /4)

__device__ __forceinline__ float sigf(float x) { return 1.0f / (1.0f + __expf(-x)); }

__global__ __launch_bounds__(128, 8)
void yolo_decode_r11(const float* __restrict__ o13,
                     const float* __restrict__ o26,
                     const float* __restrict__ o52,
                     const float* __restrict__ a13,
                     const float* __restrict__ a26,
                     const float* __restrict__ a52,
                     const float* __restrict__ threshp,
                     const int*   __restrict__ casep,
                     float* __restrict__ boxes,   // [N,6]
                     float* __restrict__ mask,    // [N]
                     int B, int quadBlocks)
{
    const int C13 = B * 13 * 13;
    const int C26 = B * 26 * 26;
    const int C52 = B * 52 * 52;
    const int Q26 = C26 >> 2;
    const int Q52 = C52 >> 2;

    const int iv = __ldg(casep);
    const float case_f = (iv > 0 && iv < 1000000) ? (float)iv : __int_as_float(iv);
    const float inv_case = 1.0f / case_f;
    const float thresh = __ldg(threshp);

    if (blockIdx.x < quadBlocks) {
        // ---------------- float4 quad path: scales 26 & 52 ----------------
        const int p = blockIdx.x * blockDim.x + threadIdx.x;
        const int nquad = 3 * (Q26 + Q52);
        if (p >= nquad) return;

        const float* in; const float* anch;
        int S, HW, Qc, q, rowoff; float t;
        if (p < 3 * Q26) { in = o26; anch = a26; S = 26; HW = 676;  Qc = Q26;
                           q = p;            rowoff = C13 * 3;         t = 16.0f; }
        else             { in = o52; anch = a52; S = 52; HW = 2704; Qc = Q52;
                           q = p - 3 * Q26;  rowoff = (C13 + C26) * 3; t = 8.0f;  }
        const float scale = t * inv_case;

        const int a     = q / Qc;
        const int quadi = q - a * Qc;
        const int local = quadi << 2;
        const int b     = local / HW;
        const int pos   = local - b * HW;      // pos%4==0, pos+3 < HW

        const float* ptr = in + (size_t)(b * 255 + a * 85) * HW + pos;  // 16B aligned

        // ---- phase 1: box channels, computed & written BEFORE argmax ----
        {
            const float4 q0 = *(const float4*)(ptr);
            const float4 q1 = *(const float4*)(ptr + HW);
            const float4 q2 = *(const float4*)(ptr + 2 * HW);
            const float4 q3 = *(const float4*)(ptr + 3 * HW);
            const float4 q4 = *(const float4*)(ptr + 4 * HW);

            const float ax = __ldg(anch + a * 2 + 0);
            const float ay = __ldg(anch + a * 2 + 1);
            const int h0 = pos / S;
            const int w0 = pos - h0 * S;

            const float oo[4] = {q0.x, q0.y, q0.z, q0.w};
            const float ox[4] = {q1.x, q1.y, q1.z, q1.w};
            const float oy[4] = {q2.x, q2.y, q2.z, q2.w};
            const float ow[4] = {q3.x, q3.y, q3.z, q3.w};
            const float oh[4] = {q4.x, q4.y, q4.z, q4.w};

            #pragma unroll
            for (int i = 0; i < 4; ++i) {
                int wi = w0 + i, hi = h0;
                if (wi >= S) { wi -= S; hi += 1; }   // at most one wrap (4 <= S)
                const int row = rowoff + (local + i) * 3 + a;
                float* r = boxes + (size_t)row * 6;
                *(float2*)(r)     = make_float2(sigf(oo[i]), ((float)wi + ox[i]) * scale);
                *(float2*)(r + 2) = make_float2(((float)hi + oy[i]) * scale,
                                                ax * __expf(ow[i]) * inv_case);
                r[4] = ay * __expf(oh[i]) * inv_case;
                mask[row] = (oo[i] > thresh) ? 1.0f : 0.0f;
            }
        }

        // ---- phase 2: argmax over 80 class channels, MLP=10 float4 ----
        // Outer loop NOT unrolled: exactly one v[10] batch live.
        // Strict '>' keeps FIRST max (jnp.argmax tie rule).
        float mx0 = -3.4e38f, mx1 = -3.4e38f, mx2 = -3.4e38f, mx3 = -3.4e38f;
        int   c0 = 0, c1 = 0, c2 = 0, c3 = 0;
        const float* pc = ptr + 5 * HW;
        #pragma unroll 1
        for (int d0 = 0; d0 < 80; d0 += 10) {
            float4 v[10];
            #pragma unroll
            for (int i = 0; i < 10; ++i)
                v[i] = *(const float4*)(pc + (d0 + i) * HW);
            #pragma unroll
            for (int i = 0; i < 10; ++i) {
                const int d = d0 + i;
                if (v[i].x > mx0) { mx0 = v[i].x; c0 = d; }
                if (v[i].y > mx1) { mx1 = v[i].y; c1 = d; }
                if (v[i].z > mx2) { mx2 = v[i].z; c2 = d; }
                if (v[i].w > mx3) { mx3 = v[i].w; c3 = d; }
            }
        }

        // ---- phase 3: class indices ----
        const int cl[4] = {c0, c1, c2, c3};
        #pragma unroll
        for (int i = 0; i < 4; ++i) {
            const int row = rowoff + (local + i) * 3 + a;
            boxes[(size_t)row * 6 + 5] = (float)cl[i];
        }
    } else {
        // ---------------- scalar path: scale 13 ----------------
        const int idx = (blockIdx.x - quadBlocks) * blockDim.x + threadIdx.x;
        if (idx >= 3 * C13) return;

        const int a     = idx / C13;
        const int local = idx - a * C13;
        const int HW = 169, S = 13;
        const int b   = local / HW;
        const int pos = local - b * HW;
        const int h   = pos / S;
        const int w   = pos - h * S;
        const float scale = 32.0f * inv_case;

        const float* ptr = o13 + (size_t)(b * 255 + a * 85) * HW + pos;
        const int row = local * 3 + a;
        float* r = boxes + (size_t)row * 6;

        {
            const float v0 = __ldg(ptr);
            const float v1 = __ldg(ptr + HW);
            const float v2 = __ldg(ptr + 2 * HW);
            const float v3 = __ldg(ptr + 3 * HW);
            const float v4 = __ldg(ptr + 4 * HW);
            *(float2*)(r)     = make_float2(sigf(v0), ((float)w + v1) * scale);
            *(float2*)(r + 2) = make_float2(((float)h + v2) * scale,
                                            __ldg(a13 + a * 2 + 0) * __expf(v3) * inv_case);
            r[4] = __ldg(a13 + a * 2 + 1) * __expf(v4) * inv_case;
            mask[row] = (v0 > thresh) ? 1.0f : 0.0f;
        }

        float maxv = -3.4e38f; int cls = 0;
        const float* pc = ptr + 5 * HW;
        #pragma unroll 1
        for (int d0 = 0; d0 < 80; d0 += 16) {
            float v[16];
            #pragma unroll
            for (int i = 0; i < 16; ++i) v[i] = __ldg(pc + (d0 + i) * HW);
            #pragma unroll
            for (int i = 0; i < 16; ++i)
                if (v[i] > maxv) { maxv = v[i]; cls = d0 + i; }
        }
        r[5] = (float)cls;
    }
}

extern "C" void kernel_launch(void* const* d_in, const int* in_sizes, int n_in,
                              void* d_out, int out_size)
{
    const float* o13 = (const float*)d_in[0];
    const float* o26 = (const float*)d_in[1];
    const float* o52 = (const float*)d_in[2];
    const float* a13 = (const float*)d_in[3];
    const float* a26 = (const float*)d_in[4];
    const float* a52 = (const float*)d_in[5];
    const float* th  = (const float*)d_in[6];
    const int*   cs  = (const int*)  d_in[7];

    const int B = in_sizes[0] / (255 * 13 * 13);

    const int C13 = B * 13 * 13;
    const int C26 = B * 26 * 26;
    const int C52 = B * 52 * 52;
    const int N = (C13 + C26 + C52) * 3;

    float* boxes = (float*)d_out;                   // [N,6]
    float* mask  = (float*)d_out + (size_t)N * 6;   // [N]

    const int TPB = 128;
    const int nquad = 3 * ((C26 >> 2) + (C52 >> 2));
    const int quadBlocks = (nquad + TPB - 1) / TPB;
    const int s13Blocks  = (3 * C13 + TPB - 1) / TPB;

    yolo_decode_r11<<<quadBlocks + s13Blocks, TPB>>>(
        o13, o26, o52, a13, a26, a52, th, cs, boxes, mask, B, quadBlocks);
}

// round 12
// speedup vs baseline: 2.4901x; 1.0526x over previous
#include <cuda_runtime.h>
#include <cuda_bf16.h>
#include <cstddef>

// Fused YOLOv3 decode. R11 (28.8us, DRAM 58%) is GRID-limited: quad path only
// makes 97K threads (~21 warps/SM). R12 doubles threads at constant LDG count:
// each quad of 4 cells is handled by TWO threads splitting the 80 class
// channels (lanes 0-15: classes 0-39, lanes 16-31: classes 40-79 of the SAME
// 16 quads), merged with one shfl_xor(16) per cell. Box channels handled by
// the low half-warp. Everything else keeps the R11 recipe: early box writes,
// #pragma unroll 1 argmax loop (no ptxas front-batching -> no spill), MLP=10
// float4 batches, 64-reg cap.
//   blocks [0, quadBlocks)  : split-channel float4 path, scales 26 & 52
//   blocks [quadBlocks, ..) : scalar path, scale 13 (HW=169 not /4)

__device__ __forceinline__ float sigf(float x) { return 1.0f / (1.0f + __expf(-x)); }

__global__ __launch_bounds__(128, 8)
void yolo_decode_r12(const float* __restrict__ o13,
                     const float* __restrict__ o26,
                     const float* __restrict__ o52,
                     const float* __restrict__ a13,
                     const float* __restrict__ a26,
                     const float* __restrict__ a52,
                     const float* __restrict__ threshp,
                     const int*   __restrict__ casep,
                     float* __restrict__ boxes,   // [N,6]
                     float* __restrict__ mask,    // [N]
                     int B, int quadBlocks)
{
    const int C13 = B * 13 * 13;
    const int C26 = B * 26 * 26;
    const int C52 = B * 52 * 52;
    const int Q26 = C26 >> 2;
    const int Q52 = C52 >> 2;

    const int iv = __ldg(casep);
    const float case_f = (iv > 0 && iv < 1000000) ? (float)iv : __int_as_float(iv);
    const float inv_case = 1.0f / case_f;
    const float thresh = __ldg(threshp);

    if (blockIdx.x < quadBlocks) {
        // ------- split-channel float4 quad path: scales 26 & 52 -------
        const int nquad = 3 * (Q26 + Q52);
        const int gw   = (blockIdx.x * blockDim.x + threadIdx.x) >> 5;  // global warp
        const int lane = threadIdx.x & 31;
        const int hh   = lane >> 4;          // channel half: 0 -> 0..39, 1 -> 40..79
        const int ql   = lane & 15;          // quad-within-warp

        int qi = gw * 16 + ql;               // quad work-item
        const bool act = (qi < nquad);
        if (!act) qi = nquad - 1;            // clamp: keeps lane pair (l, l^16) coherent

        const float* in; const float* anch;
        int S, HW, Qc, q, rowoff; float t;
        if (qi < 3 * Q26) { in = o26; anch = a26; S = 26; HW = 676;  Qc = Q26;
                            q = qi;           rowoff = C13 * 3;         t = 16.0f; }
        else              { in = o52; anch = a52; S = 52; HW = 2704; Qc = Q52;
                            q = qi - 3 * Q26; rowoff = (C13 + C26) * 3; t = 8.0f;  }
        const float scale = t * inv_case;

        const int a     = q / Qc;
        const int quadi = q - a * Qc;
        const int local = quadi << 2;
        const int b     = local / HW;
        const int pos   = local - b * HW;      // pos%4==0, pos+3 < HW

        const float* ptr = in + (size_t)(b * 255 + a * 85) * HW + pos;  // 16B aligned

        // ---- phase 1: box channels (low half-warp only), written early ----
        if (hh == 0 && act) {
            const float4 q0 = *(const float4*)(ptr);
            const float4 q1 = *(const float4*)(ptr + HW);
            const float4 q2 = *(const float4*)(ptr + 2 * HW);
            const float4 q3 = *(const float4*)(ptr + 3 * HW);
            const float4 q4 = *(const float4*)(ptr + 4 * HW);

            const float ax = __ldg(anch + a * 2 + 0);
            const float ay = __ldg(anch + a * 2 + 1);
            const int h0 = pos / S;
            const int w0 = pos - h0 * S;

            const float oo[4] = {q0.x, q0.y, q0.z, q0.w};
            const float ox[4] = {q1.x, q1.y, q1.z, q1.w};
            const float oy[4] = {q2.x, q2.y, q2.z, q2.w};
            const float ow[4] = {q3.x, q3.y, q3.z, q3.w};
            const float oh[4] = {q4.x, q4.y, q4.z, q4.w};

            #pragma unroll
            for (int i = 0; i < 4; ++i) {
                int wi = w0 + i, hi = h0;
                if (wi >= S) { wi -= S; hi += 1; }   // at most one wrap (4 <= S)
                const int row = rowoff + (local + i) * 3 + a;
                float* r = boxes + (size_t)row * 6;
                *(float2*)(r)     = make_float2(sigf(oo[i]), ((float)wi + ox[i]) * scale);
                *(float2*)(r + 2) = make_float2(((float)hi + oy[i]) * scale,
                                                ax * __expf(ow[i]) * inv_case);
                r[4] = ay * __expf(oh[i]) * inv_case;
                mask[row] = (oo[i] > thresh) ? 1.0f : 0.0f;
            }
        }

        // ---- phase 2: argmax over THIS thread's 40 class channels ----
        // MLP=10 float4 per iteration; outer loop not unrolled (no spill).
        // Strict '>' keeps FIRST max within the half.
        float mx[4] = {-3.4e38f, -3.4e38f, -3.4e38f, -3.4e38f};
        int   cl[4] = {0, 0, 0, 0};
        const float* pc = ptr + (5 + hh * 40) * HW;
        const int dbase = hh * 40;
        #pragma unroll 1
        for (int d0 = 0; d0 < 40; d0 += 10) {
            float4 v[10];
            #pragma unroll
            for (int i = 0; i < 10; ++i)
                v[i] = *(const float4*)(pc + (d0 + i) * HW);
            #pragma unroll
            for (int i = 0; i < 10; ++i) {
                const int d = dbase + d0 + i;
                if (v[i].x > mx[0]) { mx[0] = v[i].x; cl[0] = d; }
                if (v[i].y > mx[1]) { mx[1] = v[i].y; cl[1] = d; }
                if (v[i].z > mx[2]) { mx[2] = v[i].z; cl[2] = d; }
                if (v[i].w > mx[3]) { mx[3] = v[i].w; cl[3] = d; }
            }
        }

        // ---- phase 3: merge halves (lanes l <-> l^16), low half writes ----
        #pragma unroll
        for (int i = 0; i < 4; ++i) {
            const float mo = __shfl_xor_sync(0xffffffffu, mx[i], 16);
            const int   co = __shfl_xor_sync(0xffffffffu, cl[i], 16);
            // low half holds classes 0..39 (earlier indices): high wins only
            // on strictly greater -> first-max tie rule preserved.
            if (mo > mx[i]) { mx[i] = mo; cl[i] = co; }
        }
        if (hh == 0 && act) {
            #pragma unroll
            for (int i = 0; i < 4; ++i) {
                const int row = rowoff + (local + i) * 3 + a;
                boxes[(size_t)row * 6 + 5] = (float)cl[i];
            }
        }
    } else {
        // ---------------- scalar path: scale 13 ----------------
        const int idx = (blockIdx.x - quadBlocks) * blockDim.x + threadIdx.x;
        if (idx >= 3 * C13) return;

        const int a     = idx / C13;
        const int local = idx - a * C13;
        const int HW = 169, S = 13;
        const int b   = local / HW;
        const int pos = local - b * HW;
        const int h   = pos / S;
        const int w   = pos - h * S;
        const float scale = 32.0f * inv_case;

        const float* ptr = o13 + (size_t)(b * 255 + a * 85) * HW + pos;
        const int row = local * 3 + a;
        float* r = boxes + (size_t)row * 6;

        {
            const float v0 = __ldg(ptr);
            const float v1 = __ldg(ptr + HW);
            const float v2 = __ldg(ptr + 2 * HW);
            const float v3 = __ldg(ptr + 3 * HW);
            const float v4 = __ldg(ptr + 4 * HW);
            *(float2*)(r)     = make_float2(sigf(v0), ((float)w + v1) * scale);
            *(float2*)(r + 2) = make_float2(((float)h + v2) * scale,
                                            __ldg(a13 + a * 2 + 0) * __expf(v3) * inv_case);
            r[4] = __ldg(a13 + a * 2 + 1) * __expf(v4) * inv_case;
            mask[row] = (v0 > thresh) ? 1.0f : 0.0f;
        }

        float maxv = -3.4e38f; int cls = 0;
        const float* pc = ptr + 5 * HW;
        #pragma unroll 1
        for (int d0 = 0; d0 < 80; d0 += 16) {
            float v[16];
            #pragma unroll
            for (int i = 0; i < 16; ++i) v[i] = __ldg(pc + (d0 + i) * HW);
            #pragma unroll
            for (int i = 0; i < 16; ++i)
                if (v[i] > maxv) { maxv = v[i]; cls = d0 + i; }
        }
        r[5] = (float)cls;
    }
}

extern "C" void kernel_launch(void* const* d_in, const int* in_sizes, int n_in,
                              void* d_out, int out_size)
{
    const float* o13 = (const float*)d_in[0];
    const float* o26 = (const float*)d_in[1];
    const float* o52 = (const float*)d_in[2];
    const float* a13 = (const float*)d_in[3];
    const float* a26 = (const float*)d_in[4];
    const float* a52 = (const float*)d_in[5];
    const float* th  = (const float*)d_in[6];
    const int*   cs  = (const int*)  d_in[7];

    const int B = in_sizes[0] / (255 * 13 * 13);

    const int C13 = B * 13 * 13;
    const int C26 = B * 26 * 26;
    const int C52 = B * 52 * 52;
    const int N = (C13 + C26 + C52) * 3;

    float* boxes = (float*)d_out;                   // [N,6]
    float* mask  = (float*)d_out + (size_t)N * 6;   // [N]

    const int TPB = 128;
    const int nquad = 3 * ((C26 >> 2) + (C52 >> 2));
    const int quadWarps   = (nquad + 15) / 16;       // 16 quads per warp, 2 threads/quad
    const int quadThreads = quadWarps * 32;
    const int quadBlocks  = (quadThreads + TPB - 1) / TPB;
    const int s13Blocks   = (3 * C13 + TPB - 1) / TPB;

    yolo_decode_r12<<<quadBlocks + s13Blocks, TPB>>>(
        o13, o26, o52, a13, a26, a52, th, cs, boxes, mask, B, quadBlocks);
}